// round 6
// baseline (speedup 1.0000x reference)
#include <cuda_runtime.h>
#include <cuda_bf16.h>

#define NN 50000
#define EE 1600000
#define DD 32
#define NLAYERS 8
#define TOPK 8
#define VOCAB 100

// ---------------- device scratch (static, no allocations) ----------------
__device__ float g_hi[NN*DD];
__device__ float g_hj[NN*DD];
__device__ float g_hn[NN*DD];
__device__ float g_h [NN*DD];
// e/f stored as pre-split bf16 (hi,lo) pairs in MMA C/A-fragment order:
// per 16-edge tile: uint4[4 nf][32 lane] = {hi01, hi23, lo01, lo23}
//   where thread(lane): t=lane&3, r0=lane>>2, r1=r0+8, cols n0=8nf+2t:
//   hi01 = bf16x2{ v(r0,n0) lo-half, v(r0,n0+1) hi-half }, hi23 = rows r1, lo* = residuals
__device__ uint4 g_e[EE*8];
__device__ uint4 g_f[EE*8];
__device__ float g_logits[EE];
__device__ int   g_srcS[EE];
__device__ int   g_dstS[EE];
__device__ int   g_etokS[EE];
__device__ int   g_hist[NN];       // static zero-init; re-zeroed by k_scan each call
__device__ int   g_row [NN+1];
__device__ int   g_cursor[NN];
__device__ float g_rowmax[NN];

#define EB 6250   // edge blocks (256 thr)
#define WB 6250   // node warp-blocks (8 nodes per 256-thr block)

// split (x,y) into bf16x2 hi pair + bf16x2 residual pair. lo half of reg = x.
__device__ __forceinline__ void split2(float x, float y, unsigned& hi, unsigned& lo) {
    unsigned h;
    asm("cvt.rn.bf16x2.f32 %0, %1, %2;" : "=r"(h) : "f"(y), "f"(x));  // hi-half=y, lo-half=x
    float hx = __uint_as_float(h << 16);
    float hy = __uint_as_float(h & 0xffff0000u);
    float lx = x - hx, ly = y - hy;
    unsigned l;
    asm("cvt.rn.bf16x2.f32 %0, %1, %2;" : "=r"(l) : "f"(ly), "f"(lx));
    hi = h; lo = l;
}

#define MMA_BF16(ACC, A0, A1, A2, A3, B0, B1)                                        \
    asm volatile("mma.sync.aligned.m16n8k16.row.col.f32.bf16.bf16.f32 "              \
                 "{%0,%1,%2,%3}, {%4,%5,%6,%7}, {%8,%9}, {%0,%1,%2,%3};"             \
                 : "+f"(ACC[0]), "+f"(ACC[1]), "+f"(ACC[2]), "+f"(ACC[3])            \
                 : "r"(A0), "r"(A1), "r"(A2), "r"(A3), "r"(B0), "r"(B1))

// ---------------- launch 1: hist (blocks 0..EB-1) + init_proj ----------------
__global__ void k_hist_init(const int* __restrict__ dst,
                            const int* __restrict__ h_tok, const float* __restrict__ tok_emb,
                            const float* __restrict__ Wni, const float* __restrict__ Wnj,
                            const float* __restrict__ Wn, const float* __restrict__ b) {
    if (blockIdx.x < EB) {
        int i = blockIdx.x * 256 + threadIdx.x;
        if (i < EE) atomicAdd(&g_hist[dst[i]], 1);
        return;
    }
    __shared__ float wi[32][32], wj[32][32], wn[32][32], bs[32];
    int tid = threadIdx.x;
    for (int i = tid; i < 1024; i += 256) {
        wi[i >> 5][i & 31] = Wni[i];
        wj[i >> 5][i & 31] = Wnj[i];
        wn[i >> 5][i & 31] = Wn[i];
    }
    if (tid < 32) bs[tid] = b[tid];
    __syncthreads();
    int node = (blockIdx.x - EB) * 8 + (tid >> 5);
    int lane = tid & 31;
    if (node >= NN) return;
    float hv = fmaxf(tok_emb[h_tok[node] * DD + lane], 0.f);
    float ai = bs[lane], aj = 0.f, an = 0.f;
#pragma unroll
    for (int k = 0; k < 32; k++) {
        float hk = __shfl_sync(0xffffffffu, hv, k);
        ai += hk * wi[k][lane];
        aj += hk * wj[k][lane];
        an += hk * wn[k][lane];
    }
    g_hi[node * DD + lane] = ai;
    g_hj[node * DD + lane] = aj;
    g_hn[node * DD + lane] = an;
}

// ---------------- launch 2: scan ----------------
__global__ void k_scan() {
    __shared__ int sm[1024];
    int t = threadIdx.x;
    const int CH = (NN + 1023) / 1024;
    int b0 = t * CH;
    int b1 = min(b0 + CH, NN);
    int sum = 0;
    for (int i = b0; i < b1; i++) sum += g_hist[i];
    sm[t] = sum;
    __syncthreads();
    for (int off = 1; off < 1024; off <<= 1) {
        int v = (t >= off) ? sm[t - off] : 0;
        __syncthreads();
        sm[t] += v;
        __syncthreads();
    }
    int pre = sm[t] - sum;
    for (int i = b0; i < b1; i++) {
        g_row[i] = pre;
        g_cursor[i] = pre;
        pre += g_hist[i];
        g_hist[i] = 0;            // re-zero for next call
    }
    if (t == 1023) g_row[NN] = sm[1023];
}

// ---------------- launch 3: fused scatter+gather ----------------
__global__ void k_scatter_gather(const int* __restrict__ src, const int* __restrict__ dst,
                                 const int* __restrict__ e_tok) {
    int i = blockIdx.x * blockDim.x + threadIdx.x;
    if (i >= EE) return;
    int d = dst[i];
    int p = atomicAdd(&g_cursor[d], 1);
    g_srcS[p] = src[i];
    g_dstS[p] = d;
    g_etokS[p] = e_tok[i];
}

// ---------------- edge kernel: bf16 m16n8k16, 2-way split, 3 terms ----------
// MODE: 0 = first (A from token table), 1 = mid, 2 = last (skip f store)
// dyn smem: uint4 bfragB[2][4][32] (4KB) | float As[32] | layer0: etabHI/LO[VOCAB*16]
template <int MODE>
__global__ void k_edge(const float* __restrict__ Wf, const float* __restrict__ attn,
                       const float* __restrict__ e_emb, int swap) {
    extern __shared__ uint4 dsm4[];
    uint4*    bfragB = dsm4;                          // [ks2*128 + nb*32 + lane]
    float*    As     = (float*)(dsm4 + 256);          // 32
    unsigned* etabHI = (unsigned*)(As + 32);          // VOCAB*16 (MODE 0 only)
    unsigned* etabLO = etabHI + VOCAB * 16;

    int tid = threadIdx.x;
    {   // stage B fragments: one entry per thread
        int ks2 = tid >> 7, nb = (tid >> 5) & 3, l = tid & 31;
        int tt = l & 3, n = nb * 8 + (l >> 2);
        int k0 = ks2 * 16 + 2 * tt;
        float w00 = Wf[k0 * 32 + n],       w01 = Wf[(k0 + 1) * 32 + n];
        float w80 = Wf[(k0 + 8) * 32 + n], w81 = Wf[(k0 + 9) * 32 + n];
        unsigned hb0, lb0, hb1, lb1;
        split2(w00, w01, hb0, lb0);
        split2(w80, w81, hb1, lb1);
        bfragB[ks2 * 128 + nb * 32 + l] = make_uint4(hb0, hb1, lb0, lb1);
    }
    if (tid < 32) As[tid] = attn[tid];
    if (MODE == 0) {
        for (int i = tid; i < VOCAB * 16; i += 256) {
            int tok = i >> 4, cp = i & 15;
            float x = e_emb[tok * 32 + 2 * cp], y = e_emb[tok * 32 + 2 * cp + 1];
            unsigned h, l;
            split2(x, y, h, l);
            etabHI[i] = h;
            etabLO[i] = l;
        }
    }
    __syncthreads();

    int warp = tid >> 5;
    int lane = tid & 31;
    int base = (blockIdx.x * 8 + warp) * 16;
    if (base >= EE) return;
    int tile = base >> 4;
    int r0 = lane >> 2, t = lane & 3;
    int e0 = base + r0, e1 = e0 + 8;

    int s0 = g_srcS[e0], s1 = g_srcS[e1];
    int d0 = g_dstS[e0], d1 = g_dstS[e1];

    uint4 U[4];
    if (MODE == 0) {
        int t0 = g_etokS[e0] * 16, t1 = g_etokS[e1] * 16;
#pragma unroll
        for (int nf = 0; nf < 4; nf++) {
            int idx = 4 * nf + t;
            U[nf] = make_uint4(etabHI[t0 + idx], etabHI[t1 + idx],
                               etabLO[t0 + idx], etabLO[t1 + idx]);
        }
    } else {
        const uint4* ein = swap ? g_f : g_e;
#pragma unroll
        for (int nf = 0; nf < 4; nf++)
            U[nf] = ein[(size_t)tile * 128 + nf * 32 + lane];
    }

    float acc[4][4];
#pragma unroll
    for (int nb = 0; nb < 4; nb++)
#pragma unroll
        for (int q = 0; q < 4; q++) acc[nb][q] = 0.f;

#pragma unroll
    for (int ks2 = 0; ks2 < 2; ks2++) {
        unsigned ah0 = U[2 * ks2].x, ah1 = U[2 * ks2].y;
        unsigned ah2 = U[2 * ks2 + 1].x, ah3 = U[2 * ks2 + 1].y;
        unsigned al0 = U[2 * ks2].z, al1 = U[2 * ks2].w;
        unsigned al2 = U[2 * ks2 + 1].z, al3 = U[2 * ks2 + 1].w;
#pragma unroll
        for (int nb = 0; nb < 4; nb++) {
            uint4 B = bfragB[ks2 * 128 + nb * 32 + lane];
            MMA_BF16(acc[nb], ah0, ah1, ah2, ah3, B.x, B.y);   // hi * hi
            MMA_BF16(acc[nb], ah0, ah1, ah2, ah3, B.z, B.w);   // hi * lo
            MMA_BF16(acc[nb], al0, al1, al2, al3, B.x, B.y);   // lo * hi
        }
    }

    // epilogue: + hi[src] + hj[dst], leakyrelu, logit, split-store (no shuffles)
    const float2* hi2 = (const float2*)g_hi;
    const float2* hj2 = (const float2*)g_hj;
    float2 hia[4], hja[4], hib[4], hjb[4];
#pragma unroll
    for (int nf = 0; nf < 4; nf++) {
        hia[nf] = hi2[s0 * 16 + nf * 4 + t];
        hja[nf] = hj2[d0 * 16 + nf * 4 + t];
        hib[nf] = hi2[s1 * 16 + nf * 4 + t];
        hjb[nf] = hj2[d1 * 16 + nf * 4 + t];
    }

    uint4* fout = swap ? g_e : g_f;
    float p0 = 0.f, p1 = 0.f;
#pragma unroll
    for (int nf = 0; nf < 4; nf++) {
        int n0 = nf * 8 + t * 2;
        float v0 = acc[nf][0] + hia[nf].x + hja[nf].x;
        float v1 = acc[nf][1] + hia[nf].y + hja[nf].y;
        float v2 = acc[nf][2] + hib[nf].x + hjb[nf].x;
        float v3 = acc[nf][3] + hib[nf].y + hjb[nf].y;
        v0 = (v0 > 0.f) ? v0 : 0.01f * v0;
        v1 = (v1 > 0.f) ? v1 : 0.01f * v1;
        v2 = (v2 > 0.f) ? v2 : 0.01f * v2;
        v3 = (v3 > 0.f) ? v3 : 0.01f * v3;
        float a0 = As[n0], a1 = As[n0 + 1];
        p0 += v0 * a0 + v1 * a1;
        p1 += v2 * a0 + v3 * a1;
        if (MODE != 2) {
            unsigned h01, l01, h23, l23;
            split2(v0, v1, h01, l01);
            split2(v2, v3, h23, l23);
            fout[(size_t)tile * 128 + nf * 32 + lane] = make_uint4(h01, h23, l01, l23);
        }
    }
    p0 += __shfl_xor_sync(0xffffffffu, p0, 1);
    p0 += __shfl_xor_sync(0xffffffffu, p0, 2);
    p1 += __shfl_xor_sync(0xffffffffu, p1, 1);
    p1 += __shfl_xor_sync(0xffffffffu, p1, 2);
    if (t == 0) {
        g_logits[e0] = p0;
        g_logits[e1] = p1;
    }
}

// ---------------- agg (+relu) fused with next layer's projections ----------
__global__ void k_aggproj(const float* __restrict__ Wni, const float* __restrict__ Wnj,
                          const float* __restrict__ Wn, const float* __restrict__ b,
                          int last) {
    __shared__ float wT[3][32][36];   // transposed, pad 36 for LDS.128
    __shared__ float bs[32];
    int tid = threadIdx.x;
    if (!last) {
        for (int i = tid; i < 1024; i += 256) {
            int r = i >> 5, c = i & 31;
            wT[0][c][r] = Wni[i];
            wT[1][c][r] = Wnj[i];
            wT[2][c][r] = Wn[i];
        }
        if (tid < 32) bs[tid] = b[tid];
    }
    __syncthreads();
    int node = blockIdx.x * 8 + (tid >> 5);
    int lane = tid & 31;
    if (node >= NN) return;
    int beg = g_row[node], end = g_row[node + 1];
    float m = -1e30f;
    for (int i = beg + lane; i < end; i += 32) m = fmaxf(m, g_logits[i]);
#pragma unroll
    for (int o = 16; o; o >>= 1) m = fmaxf(m, __shfl_xor_sync(0xffffffffu, m, o));
    float s = 0.f, acc0 = 0.f, acc1 = 0.f;
    for (int chunk = beg; chunk < end; chunk += 32) {
        int i = chunk + lane;
        float w = 0.f;
        int sv = 0;
        if (i < end) {
            w = __expf(g_logits[i] - m);
            sv = g_srcS[i];
        }
        s += w;
#pragma unroll
        for (int e = 0; e < 32; e += 2) {
            float we0 = __shfl_sync(0xffffffffu, w, e);
            int   se0 = __shfl_sync(0xffffffffu, sv, e);
            float we1 = __shfl_sync(0xffffffffu, w, e + 1);
            int   se1 = __shfl_sync(0xffffffffu, sv, e + 1);
            acc0 += we0 * g_hn[se0 * DD + lane];
            acc1 += we1 * g_hn[se1 * DD + lane];
        }
    }
#pragma unroll
    for (int o = 16; o; o >>= 1) s += __shfl_xor_sync(0xffffffffu, s, o);
    float hv = (end > beg) ? fmaxf((acc0 + acc1) / s, 0.f) : 0.f;

    if (last) {
        g_h[node * DD + lane] = hv;
        float v = hv;
#pragma unroll
        for (int o = 16; o; o >>= 1) v = fmaxf(v, __shfl_xor_sync(0xffffffffu, v, o));
        if (lane == 0) g_rowmax[node] = v;
    } else {
        const float4* wri = (const float4*)wT[0][lane];
        const float4* wrj = (const float4*)wT[1][lane];
        const float4* wrn = (const float4*)wT[2][lane];
        float ai = bs[lane], aj = 0.f, an = 0.f;
#pragma unroll
        for (int q = 0; q < 8; q++) {
            float4 a4 = wri[q], b4 = wrj[q], c4 = wrn[q];
            float h0 = __shfl_sync(0xffffffffu, hv, 4 * q + 0);
            float h1 = __shfl_sync(0xffffffffu, hv, 4 * q + 1);
            float h2 = __shfl_sync(0xffffffffu, hv, 4 * q + 2);
            float h3 = __shfl_sync(0xffffffffu, hv, 4 * q + 3);
            ai += h0 * a4.x + h1 * a4.y + h2 * a4.z + h3 * a4.w;
            aj += h0 * b4.x + h1 * b4.y + h2 * b4.z + h3 * b4.w;
            an += h0 * c4.x + h1 * c4.y + h2 * c4.z + h3 * c4.w;
        }
        g_hi[node * DD + lane] = ai;
        g_hj[node * DD + lane] = aj;
        g_hn[node * DD + lane] = an;
    }
}

// ---------------- SortPooling + MLP head ----------------
__global__ void k_head(const float* __restrict__ Wlin, const float* __restrict__ blin,
                       const float* __restrict__ W1, const float* __restrict__ b1,
                       const float* __restrict__ W2, const float* __restrict__ b2,
                       const float* __restrict__ Wc, const float* __restrict__ bc,
                       float* __restrict__ out) {
    __shared__ float sv[256];
    __shared__ int si[256];
    __shared__ int picked[TOPK];
    __shared__ float xs[TOPK * DD];
    __shared__ float y1[32], y2[32], y3[32];
    int tid = threadIdx.x;

    for (int t = 0; t < TOPK; t++) {
        float best = -1e30f;
        int bidx = 0x7fffffff;
        for (int i = tid; i < NN; i += 256) {
            bool skip = false;
            for (int p = 0; p < t; p++)
                if (picked[p] == i) skip = true;
            if (skip) continue;
            float v = g_rowmax[i];
            if (v > best || (v == best && i < bidx)) { best = v; bidx = i; }
        }
        sv[tid] = best;
        si[tid] = bidx;
        __syncthreads();
        for (int off = 128; off; off >>= 1) {
            if (tid < off) {
                float v2 = sv[tid + off];
                int i2 = si[tid + off];
                if (v2 > sv[tid] || (v2 == sv[tid] && i2 < si[tid])) {
                    sv[tid] = v2;
                    si[tid] = i2;
                }
            }
            __syncthreads();
        }
        if (tid == 0) picked[t] = si[0];
        __syncthreads();
    }

    if (tid < TOPK) {
        float r[32];
        int n = picked[tid];
        for (int d = 0; d < 32; d++) r[d] = g_h[n * DD + d];
        for (int a = 1; a < 32; a++) {
            float key = r[a];
            int b = a - 1;
            while (b >= 0 && r[b] > key) { r[b + 1] = r[b]; b--; }
            r[b + 1] = key;
        }
        for (int d = 0; d < 32; d++) xs[tid * 32 + d] = r[d];
    }
    __syncthreads();

    if (tid < 32) {
        float a = blin[tid];
        for (int i = 0; i < 256; i++) a += xs[i] * Wlin[i * 32 + tid];
        y1[tid] = fmaxf(a, 0.f);
    }
    __syncthreads();
    if (tid < 32) {
        float a = b1[tid];
        for (int k = 0; k < 32; k++) a += y1[k] * W1[k * 32 + tid];
        y2[tid] = fmaxf(a, 0.f);
    }
    __syncthreads();
    if (tid < 32) {
        float a = b2[tid];
        for (int k = 0; k < 32; k++) a += y2[k] * W2[k * 32 + tid];
        y3[tid] = fmaxf(a, 0.f);
    }
    __syncthreads();
    if (tid < 2) {
        float a = bc[tid];
        for (int k = 0; k < 32; k++) a += y3[k] * Wc[k * 2 + tid];
        out[tid] = a;
    }
}

// ---------------- launch ----------------
extern "C" void kernel_launch(void* const* d_in, const int* in_sizes, int n_in,
                              void* d_out, int out_size) {
    (void)in_sizes; (void)n_in; (void)out_size;
    const int*   h_tok     = (const int*)d_in[0];
    const int*   e_tok     = (const int*)d_in[1];
    const int*   src       = (const int*)d_in[2];
    const int*   dst       = (const int*)d_in[3];
    const float* tok_emb   = (const float*)d_in[4];
    const float* e_tok_emb = (const float*)d_in[5];
    const float* W_ni      = (const float*)d_in[6];
    const float* W_nj      = (const float*)d_in[7];
    const float* W_fij     = (const float*)d_in[8];
    const float* b_edge    = (const float*)d_in[9];
    const float* attn      = (const float*)d_in[10];
    const float* W_node    = (const float*)d_in[11];
    const float* W_lin     = (const float*)d_in[12];
    const float* b_lin     = (const float*)d_in[13];
    const float* W1        = (const float*)d_in[14];
    const float* b1        = (const float*)d_in[15];
    const float* W2        = (const float*)d_in[16];
    const float* b2        = (const float*)d_in[17];
    const float* Wc        = (const float*)d_in[18];
    const float* bc        = (const float*)d_in[19];
    float* out = (float*)d_out;

    const int MB = (EE + 127) / 128;                       // 12500
    const size_t SM_BASE  = 256 * 16 + 32 * 4;             // 4224
    const size_t SM_FIRST = SM_BASE + 2 * VOCAB * 16 * 4;  // 17024

    k_hist_init<<<EB + WB, 256>>>(dst, h_tok, tok_emb, W_ni, W_nj, W_node, b_edge);
    k_scan<<<1, 1024>>>();
    k_scatter_gather<<<EB, 256>>>(src, dst, e_tok);

    for (int l = 0; l < NLAYERS; l++) {
        int swap = l & 1;
        if (l == 0)
            k_edge<0><<<MB, 256, SM_FIRST>>>(W_fij, attn, e_tok_emb, swap);
        else if (l == NLAYERS - 1)
            k_edge<2><<<MB, 256, SM_BASE>>>(W_fij + l * 1024, attn + l * 32, e_tok_emb, swap);
        else
            k_edge<1><<<MB, 256, SM_BASE>>>(W_fij + l * 1024, attn + l * 32, e_tok_emb, swap);
        if (l < NLAYERS - 1) {
            k_aggproj<<<WB, 256>>>(W_ni + (l + 1) * 1024, W_nj + (l + 1) * 1024,
                                   W_node + (l + 1) * 1024, b_edge + (l + 1) * 32, 0);
        } else {
            k_aggproj<<<WB, 256>>>(W_ni, W_nj, W_node, b_edge, 1);
        }
    }

    k_head<<<1, 256>>>(W_lin, b_lin, W1, b1, W2, b2, Wc, bc, out);
}

// round 7
// speedup vs baseline: 1.4478x; 1.4478x over previous
#include <cuda_runtime.h>
#include <cuda_bf16.h>

#define NN 50000
#define EE 1600000
#define DD 32
#define NLAYERS 8
#define TOPK 8
#define VOCAB 100

// ---------------- device scratch (static, no allocations) ----------------
__device__ float g_hi[NN*DD];
__device__ float g_hj[NN*DD];
__device__ float g_hn[NN*DD];
__device__ float g_h [NN*DD];
// e/f stored in MMA C-fragment order (f32):
// per 16-edge tile: float4[4 nf][32 lane] = { v(r0,n0), v(r0,n0+1), v(r1,n0), v(r1,n0+1) }
//   thread(lane): t=lane&3, r0=lane>>2, r1=r0+8, n0 = 8*nf + 2*t
// Next layer consumes this directly as a k-permuted A fragment (B rows permuted to match).
__device__ float4 g_e[EE*8];
__device__ float4 g_f[EE*8];
__device__ float g_logits[EE];
__device__ int   g_srcS[EE];
__device__ int   g_dstS[EE];
__device__ int   g_etokS[EE];
__device__ int   g_hist[NN];       // static zero-init; re-zeroed by k_scan each call
__device__ int   g_row [NN+1];
__device__ int   g_cursor[NN];
__device__ float g_rowmax[NN];

__device__ __forceinline__ unsigned f2tf32(float x) {
    unsigned r;
    asm("cvt.rna.tf32.f32 %0, %1;" : "=r"(r) : "f"(x));
    return r;
}

#define EB 6250   // edge blocks (256 thr)
#define WB 6250   // node warp-blocks (8 nodes per 256-thr block)

// ---------------- launch 1: hist (blocks 0..EB-1) + init_proj ----------------
__global__ void k_hist_init(const int* __restrict__ dst,
                            const int* __restrict__ h_tok, const float* __restrict__ tok_emb,
                            const float* __restrict__ Wni, const float* __restrict__ Wnj,
                            const float* __restrict__ Wn, const float* __restrict__ b) {
    if (blockIdx.x < EB) {
        int i = blockIdx.x * 256 + threadIdx.x;
        if (i < EE) atomicAdd(&g_hist[dst[i]], 1);
        return;
    }
    __shared__ float wi[32][32], wj[32][32], wn[32][32], bs[32];
    int tid = threadIdx.x;
    for (int i = tid; i < 1024; i += 256) {
        wi[i >> 5][i & 31] = Wni[i];
        wj[i >> 5][i & 31] = Wnj[i];
        wn[i >> 5][i & 31] = Wn[i];
    }
    if (tid < 32) bs[tid] = b[tid];
    __syncthreads();
    int node = (blockIdx.x - EB) * 8 + (tid >> 5);
    int lane = tid & 31;
    if (node >= NN) return;
    float hv = fmaxf(tok_emb[h_tok[node] * DD + lane], 0.f);
    float ai = bs[lane], aj = 0.f, an = 0.f;
#pragma unroll
    for (int k = 0; k < 32; k++) {
        float hk = __shfl_sync(0xffffffffu, hv, k);
        ai += hk * wi[k][lane];
        aj += hk * wj[k][lane];
        an += hk * wn[k][lane];
    }
    g_hi[node * DD + lane] = ai;
    g_hj[node * DD + lane] = aj;
    g_hn[node * DD + lane] = an;
}

// ---------------- launch 2: scan ----------------
__global__ void k_scan() {
    __shared__ int sm[1024];
    int t = threadIdx.x;
    const int CH = (NN + 1023) / 1024;
    int b0 = t * CH;
    int b1 = min(b0 + CH, NN);
    int sum = 0;
    for (int i = b0; i < b1; i++) sum += g_hist[i];
    sm[t] = sum;
    __syncthreads();
    for (int off = 1; off < 1024; off <<= 1) {
        int v = (t >= off) ? sm[t - off] : 0;
        __syncthreads();
        sm[t] += v;
        __syncthreads();
    }
    int pre = sm[t] - sum;
    for (int i = b0; i < b1; i++) {
        g_row[i] = pre;
        g_cursor[i] = pre;
        pre += g_hist[i];
        g_hist[i] = 0;            // re-zero for next call
    }
    if (t == 1023) g_row[NN] = sm[1023];
}

// ---------------- launch 3: fused scatter+gather ----------------
__global__ void k_scatter_gather(const int* __restrict__ src, const int* __restrict__ dst,
                                 const int* __restrict__ e_tok) {
    int i = blockIdx.x * blockDim.x + threadIdx.x;
    if (i >= EE) return;
    int d = dst[i];
    int p = atomicAdd(&g_cursor[d], 1);
    g_srcS[p] = src[i];
    g_dstS[p] = d;
    g_etokS[p] = e_tok[i];
}

// ---------------- edge kernel (tf32 3x-split mma, C-frag f layout) ----------
// flags: bit0 = swap (read g_f/write g_e), bit1 = first (e from token table), bit2 = last (skip f store)
// A is consumed in k-permuted order (slot t <- col 2t, slot t+4 <- col 2t+1);
// B is staged with the SAME row permutation, so the product is exact.
// dyn smem: float4 bfrag[4][4][32] (8KB) | float As[32] | layer0: etab[VOCAB*33]
__global__ void k_edge_mma(const float* __restrict__ Wf, const float* __restrict__ attn,
                           const float* __restrict__ e_emb, int flags) {
    extern __shared__ float4 dsm[];
    float4* bfragP = dsm;                    // ks*128 + nf*32 + lane
    float*  As     = (float*)(dsm + 512);    // 32 floats
    float*  etab   = As + 32;                // VOCAB*33 floats (layer 0 only)
    const int swap = flags & 1, first = flags & 2, lastl = flags & 4;
    int tid = threadIdx.x;
#pragma unroll
    for (int e2 = 0; e2 < 2; e2++) {
        int eid = tid + e2 * 256;
        int ks = eid >> 7, nf = (eid >> 5) & 3, ln = eid & 31;
        // permuted rows: slot (ln&3) <- col ks*8 + 2*(ln&3); slot +4 <- col +1
        int k0 = ks * 8 + 2 * (ln & 3);
        int n  = nf * 8 + (ln >> 2);
        float b0 = Wf[k0 * 32 + n];
        float b1 = Wf[(k0 + 1) * 32 + n];
        unsigned b0b = f2tf32(b0);
        unsigned b0s = f2tf32(b0 - __uint_as_float(b0b));
        unsigned b1b = f2tf32(b1);
        unsigned b1s = f2tf32(b1 - __uint_as_float(b1b));
        bfragP[ks * 128 + nf * 32 + ln] =
            make_float4(__uint_as_float(b0b), __uint_as_float(b0s),
                        __uint_as_float(b1b), __uint_as_float(b1s));
    }
    if (tid < 32) As[tid] = attn[tid];
    if (first) {
        for (int i = tid; i < VOCAB * DD; i += 256)
            etab[(i >> 5) * 33 + (i & 31)] = e_emb[i];
    }
    __syncthreads();

    int warp = tid >> 5;
    int lane = tid & 31;
    int base = (blockIdx.x * 8 + warp) * 16;
    if (base >= EE) return;
    int tile = base >> 4;

    const float4* ein4 = (const float4*)(swap ? g_f : g_e);
    float4*       fout4 = (float4*)(swap ? g_e : g_f);

    int r0 = lane >> 2;
    int t = lane & 3;
    int e0 = base + r0, e1 = e0 + 8;

    int s0 = g_srcS[e0], s1 = g_srcS[e1];
    int d0 = g_dstS[e0], d1 = g_dstS[e1];
    int t0 = 0, t1 = 0;
    if (first) { t0 = g_etokS[e0] * 33; t1 = g_etokS[e1] * 33; }

    float acc[4][4];
#pragma unroll
    for (int nf = 0; nf < 4; nf++)
#pragma unroll
        for (int q = 0; q < 4; q++) acc[nf][q] = 0.f;

#pragma unroll
    for (int ks = 0; ks < 4; ks++) {
        float4 va;   // C-frag order: {(r0,2t),(r0,2t+1),(r1,2t),(r1,2t+1)} within ks group
        if (first) {
            va.x = etab[t0 + ks * 8 + 2 * t];
            va.y = etab[t0 + ks * 8 + 2 * t + 1];
            va.z = etab[t1 + ks * 8 + 2 * t];
            va.w = etab[t1 + ks * 8 + 2 * t + 1];
        } else {
            va = ein4[(size_t)tile * 128 + ks * 32 + lane];
        }
        // A regs: a0=(r0,slot t)=va.x, a1=(r1,slot t)=va.z, a2=(r0,slot t+4)=va.y, a3=(r1,slot t+4)=va.w
        unsigned ab0 = f2tf32(va.x), ab1 = f2tf32(va.z), ab2 = f2tf32(va.y), ab3 = f2tf32(va.w);
        unsigned as0 = f2tf32(va.x - __uint_as_float(ab0));
        unsigned as1 = f2tf32(va.z - __uint_as_float(ab1));
        unsigned as2 = f2tf32(va.y - __uint_as_float(ab2));
        unsigned as3 = f2tf32(va.w - __uint_as_float(ab3));
#pragma unroll
        for (int nf = 0; nf < 4; nf++) {
            float4 bv = bfragP[ks * 128 + nf * 32 + lane];
            unsigned b0b = __float_as_uint(bv.x), b0s = __float_as_uint(bv.y);
            unsigned b1b = __float_as_uint(bv.z), b1s = __float_as_uint(bv.w);
            asm volatile(
                "mma.sync.aligned.m16n8k8.row.col.f32.tf32.tf32.f32 "
                "{%0,%1,%2,%3}, {%4,%5,%6,%7}, {%8,%9}, {%0,%1,%2,%3};"
                : "+f"(acc[nf][0]), "+f"(acc[nf][1]), "+f"(acc[nf][2]), "+f"(acc[nf][3])
                : "r"(ab0), "r"(ab1), "r"(ab2), "r"(ab3), "r"(b0b), "r"(b1b));
            asm volatile(
                "mma.sync.aligned.m16n8k8.row.col.f32.tf32.tf32.f32 "
                "{%0,%1,%2,%3}, {%4,%5,%6,%7}, {%8,%9}, {%0,%1,%2,%3};"
                : "+f"(acc[nf][0]), "+f"(acc[nf][1]), "+f"(acc[nf][2]), "+f"(acc[nf][3])
                : "r"(ab0), "r"(ab1), "r"(ab2), "r"(ab3), "r"(b0s), "r"(b1s));
            asm volatile(
                "mma.sync.aligned.m16n8k8.row.col.f32.tf32.tf32.f32 "
                "{%0,%1,%2,%3}, {%4,%5,%6,%7}, {%8,%9}, {%0,%1,%2,%3};"
                : "+f"(acc[nf][0]), "+f"(acc[nf][1]), "+f"(acc[nf][2]), "+f"(acc[nf][3])
                : "r"(as0), "r"(as1), "r"(as2), "r"(as3), "r"(b0b), "r"(b1b));
        }
    }

    // epilogue: + hi[src] + hj[dst], leakyrelu, logit, direct C-frag store (no shuffles)
    const float2* hi2 = (const float2*)g_hi;
    const float2* hj2 = (const float2*)g_hj;
    float2 hia[4], hja[4], hib[4], hjb[4];
#pragma unroll
    for (int nf = 0; nf < 4; nf++) {
        hia[nf] = hi2[s0 * 16 + nf * 4 + t];
        hja[nf] = hj2[d0 * 16 + nf * 4 + t];
        hib[nf] = hi2[s1 * 16 + nf * 4 + t];
        hjb[nf] = hj2[d1 * 16 + nf * 4 + t];
    }

    float p0 = 0.f, p1 = 0.f;
#pragma unroll
    for (int nf = 0; nf < 4; nf++) {
        int n0 = nf * 8 + t * 2;
        float v0 = acc[nf][0] + hia[nf].x + hja[nf].x;   // (r0, n0)
        float v1 = acc[nf][1] + hia[nf].y + hja[nf].y;   // (r0, n0+1)
        float v2 = acc[nf][2] + hib[nf].x + hjb[nf].x;   // (r1, n0)
        float v3 = acc[nf][3] + hib[nf].y + hjb[nf].y;   // (r1, n0+1)
        v0 = (v0 > 0.f) ? v0 : 0.01f * v0;
        v1 = (v1 > 0.f) ? v1 : 0.01f * v1;
        v2 = (v2 > 0.f) ? v2 : 0.01f * v2;
        v3 = (v3 > 0.f) ? v3 : 0.01f * v3;
        float a0 = As[n0], a1 = As[n0 + 1];
        p0 += v0 * a0 + v1 * a1;
        p1 += v2 * a0 + v3 * a1;
        if (!lastl)
            fout4[(size_t)tile * 128 + nf * 32 + lane] = make_float4(v0, v1, v2, v3);
    }
    p0 += __shfl_xor_sync(0xffffffffu, p0, 1);
    p0 += __shfl_xor_sync(0xffffffffu, p0, 2);
    p1 += __shfl_xor_sync(0xffffffffu, p1, 1);
    p1 += __shfl_xor_sync(0xffffffffu, p1, 2);
    if (t == 0) {
        g_logits[e0] = p0;
        g_logits[e1] = p1;
    }
}

// ---------------- agg (+relu) fused with next layer's projections ----------
__global__ void k_aggproj(const float* __restrict__ Wni, const float* __restrict__ Wnj,
                          const float* __restrict__ Wn, const float* __restrict__ b,
                          int last) {
    __shared__ float wi[32][32], wj[32][32], wn[32][32], bs[32];
    int tid = threadIdx.x;
    if (!last) {
        for (int i = tid; i < 1024; i += 256) {
            wi[i >> 5][i & 31] = Wni[i];
            wj[i >> 5][i & 31] = Wnj[i];
            wn[i >> 5][i & 31] = Wn[i];
        }
        if (tid < 32) bs[tid] = b[tid];
    }
    __syncthreads();
    int node = blockIdx.x * 8 + (tid >> 5);
    int lane = tid & 31;
    if (node >= NN) return;
    int beg = g_row[node], end = g_row[node + 1];
    float m = -1e30f;
    for (int i = beg + lane; i < end; i += 32) m = fmaxf(m, g_logits[i]);
#pragma unroll
    for (int o = 16; o; o >>= 1) m = fmaxf(m, __shfl_xor_sync(0xffffffffu, m, o));
    float s = 0.f, acc = 0.f;
    for (int chunk = beg; chunk < end; chunk += 32) {
        int i = chunk + lane;
        float w = 0.f;
        int sv = 0;
        if (i < end) {
            w = __expf(g_logits[i] - m);
            sv = g_srcS[i];
        }
        s += w;
#pragma unroll
        for (int e = 0; e < 32; e++) {
            float we = __shfl_sync(0xffffffffu, w, e);
            int se = __shfl_sync(0xffffffffu, sv, e);
            acc += we * g_hn[se * DD + lane];
        }
    }
#pragma unroll
    for (int o = 16; o; o >>= 1) s += __shfl_xor_sync(0xffffffffu, s, o);
    float hv = (end > beg) ? fmaxf(acc / s, 0.f) : 0.f;

    if (last) {
        g_h[node * DD + lane] = hv;
        float v = hv;
#pragma unroll
        for (int o = 16; o; o >>= 1) v = fmaxf(v, __shfl_xor_sync(0xffffffffu, v, o));
        if (lane == 0) g_rowmax[node] = v;
    } else {
        float ai = bs[lane], aj = 0.f, an = 0.f;
#pragma unroll
        for (int k = 0; k < 32; k++) {
            float hk = __shfl_sync(0xffffffffu, hv, k);
            ai += hk * wi[k][lane];
            aj += hk * wj[k][lane];
            an += hk * wn[k][lane];
        }
        g_hi[node * DD + lane] = ai;
        g_hj[node * DD + lane] = aj;
        g_hn[node * DD + lane] = an;
    }
}

// ---------------- SortPooling + MLP head ----------------
__global__ void k_head(const float* __restrict__ Wlin, const float* __restrict__ blin,
                       const float* __restrict__ W1, const float* __restrict__ b1,
                       const float* __restrict__ W2, const float* __restrict__ b2,
                       const float* __restrict__ Wc, const float* __restrict__ bc,
                       float* __restrict__ out) {
    __shared__ float sv[256];
    __shared__ int si[256];
    __shared__ int picked[TOPK];
    __shared__ float xs[TOPK * DD];
    __shared__ float y1[32], y2[32], y3[32];
    int tid = threadIdx.x;

    for (int t = 0; t < TOPK; t++) {
        float best = -1e30f;
        int bidx = 0x7fffffff;
        for (int i = tid; i < NN; i += 256) {
            bool skip = false;
            for (int p = 0; p < t; p++)
                if (picked[p] == i) skip = true;
            if (skip) continue;
            float v = g_rowmax[i];
            if (v > best || (v == best && i < bidx)) { best = v; bidx = i; }
        }
        sv[tid] = best;
        si[tid] = bidx;
        __syncthreads();
        for (int off = 128; off; off >>= 1) {
            if (tid < off) {
                float v2 = sv[tid + off];
                int i2 = si[tid + off];
                if (v2 > sv[tid] || (v2 == sv[tid] && i2 < si[tid])) {
                    sv[tid] = v2;
                    si[tid] = i2;
                }
            }
            __syncthreads();
        }
        if (tid == 0) picked[t] = si[0];
        __syncthreads();
    }

    if (tid < TOPK) {
        float r[32];
        int n = picked[tid];
        for (int d = 0; d < 32; d++) r[d] = g_h[n * DD + d];
        for (int a = 1; a < 32; a++) {
            float key = r[a];
            int b = a - 1;
            while (b >= 0 && r[b] > key) { r[b + 1] = r[b]; b--; }
            r[b + 1] = key;
        }
        for (int d = 0; d < 32; d++) xs[tid * 32 + d] = r[d];
    }
    __syncthreads();

    if (tid < 32) {
        float a = blin[tid];
        for (int i = 0; i < 256; i++) a += xs[i] * Wlin[i * 32 + tid];
        y1[tid] = fmaxf(a, 0.f);
    }
    __syncthreads();
    if (tid < 32) {
        float a = b1[tid];
        for (int k = 0; k < 32; k++) a += y1[k] * W1[k * 32 + tid];
        y2[tid] = fmaxf(a, 0.f);
    }
    __syncthreads();
    if (tid < 32) {
        float a = b2[tid];
        for (int k = 0; k < 32; k++) a += y2[k] * W2[k * 32 + tid];
        y3[tid] = fmaxf(a, 0.f);
    }
    __syncthreads();
    if (tid < 2) {
        float a = bc[tid];
        for (int k = 0; k < 32; k++) a += y3[k] * Wc[k * 2 + tid];
        out[tid] = a;
    }
}

// ---------------- launch ----------------
extern "C" void kernel_launch(void* const* d_in, const int* in_sizes, int n_in,
                              void* d_out, int out_size) {
    (void)in_sizes; (void)n_in; (void)out_size;
    const int*   h_tok     = (const int*)d_in[0];
    const int*   e_tok     = (const int*)d_in[1];
    const int*   src       = (const int*)d_in[2];
    const int*   dst       = (const int*)d_in[3];
    const float* tok_emb   = (const float*)d_in[4];
    const float* e_tok_emb = (const float*)d_in[5];
    const float* W_ni      = (const float*)d_in[6];
    const float* W_nj      = (const float*)d_in[7];
    const float* W_fij     = (const float*)d_in[8];
    const float* b_edge    = (const float*)d_in[9];
    const float* attn      = (const float*)d_in[10];
    const float* W_node    = (const float*)d_in[11];
    const float* W_lin     = (const float*)d_in[12];
    const float* b_lin     = (const float*)d_in[13];
    const float* W1        = (const float*)d_in[14];
    const float* b1        = (const float*)d_in[15];
    const float* W2        = (const float*)d_in[16];
    const float* b2        = (const float*)d_in[17];
    const float* Wc        = (const float*)d_in[18];
    const float* bc        = (const float*)d_in[19];
    float* out = (float*)d_out;

    const int MB = (EE + 127) / 128;                      // 12500
    const size_t SM_BASE  = 512 * 16 + 32 * 4;            // 8320
    const size_t SM_FIRST = SM_BASE + VOCAB * 33 * 4;     // 21520

    k_hist_init<<<EB + WB, 256>>>(dst, h_tok, tok_emb, W_ni, W_nj, W_node, b_edge);
    k_scan<<<1, 1024>>>();
    k_scatter_gather<<<EB, 256>>>(src, dst, e_tok);

    for (int l = 0; l < NLAYERS; l++) {
        int flags = (l & 1) | ((l == 0) ? 2 : 0) | ((l == NLAYERS - 1) ? 4 : 0);
        k_edge_mma<<<MB, 256, (l == 0) ? SM_FIRST : SM_BASE>>>(
            W_fij + l * 1024, attn + l * 32, e_tok_emb, flags);
        if (l < NLAYERS - 1) {
            k_aggproj<<<WB, 256>>>(W_ni + (l + 1) * 1024, W_nj + (l + 1) * 1024,
                                   W_node + (l + 1) * 1024, b_edge + (l + 1) * 32, 0);
        } else {
            k_aggproj<<<WB, 256>>>(W_ni, W_nj, W_node, b_edge, 1);
        }
    }

    k_head<<<1, 256>>>(W_lin, b_lin, W1, b1, W2, b2, Wc, bc, out);
}

// round 8
// speedup vs baseline: 1.4507x; 1.0019x over previous
#include <cuda_runtime.h>
#include <cuda_bf16.h>

#define NN 50000
#define EE 1600000
#define DD 32
#define NLAYERS 8
#define TOPK 8
#define VOCAB 100

// ---------------- device scratch (static, no allocations) ----------------
__device__ float g_hi[NN*DD];
__device__ float g_hj[NN*DD];
__device__ float g_hn[NN*DD];
__device__ float g_h [NN*DD];
// e/f stored in MMA C-fragment order (f32):
// per 16-edge tile: float4[4 nf][32 lane] = { v(r0,n0), v(r0,n0+1), v(r1,n0), v(r1,n0+1) }
//   thread(lane): t=lane&3, r0=lane>>2, r1=r0+8, n0 = 8*nf + 2*t
// Next layer consumes this directly as a k-permuted A fragment (B rows permuted to match).
__device__ float4 g_e[EE*8];
__device__ float4 g_f[EE*8];
__device__ float g_logits[EE];
__device__ int   g_srcS[EE];
__device__ int   g_dstS[EE];
__device__ int   g_etokS[EE];
__device__ int   g_hist[NN];       // static zero-init; re-zeroed by k_scan each call
__device__ int   g_row [NN+1];
__device__ int   g_cursor[NN];
__device__ float g_rowmax[NN];

__device__ __forceinline__ unsigned f2tf32(float x) {
    unsigned r;
    asm("cvt.rna.tf32.f32 %0, %1;" : "=r"(r) : "f"(x));
    return r;
}

#define EB 6250   // edge blocks (256 thr)
#define WB 6250   // node warp-blocks (8 nodes per 256-thr block)

// ---------------- launch 1: hist (blocks 0..EB-1) + init_proj ----------------
__global__ void k_hist_init(const int* __restrict__ dst,
                            const int* __restrict__ h_tok, const float* __restrict__ tok_emb,
                            const float* __restrict__ Wni, const float* __restrict__ Wnj,
                            const float* __restrict__ Wn, const float* __restrict__ b) {
    if (blockIdx.x < EB) {
        int i = blockIdx.x * 256 + threadIdx.x;
        if (i < EE) atomicAdd(&g_hist[dst[i]], 1);
        return;
    }
    __shared__ float wi[32][32], wj[32][32], wn[32][32], bs[32];
    int tid = threadIdx.x;
    for (int i = tid; i < 1024; i += 256) {
        wi[i >> 5][i & 31] = Wni[i];
        wj[i >> 5][i & 31] = Wnj[i];
        wn[i >> 5][i & 31] = Wn[i];
    }
    if (tid < 32) bs[tid] = b[tid];
    __syncthreads();
    int node = (blockIdx.x - EB) * 8 + (tid >> 5);
    int lane = tid & 31;
    if (node >= NN) return;
    float hv = fmaxf(tok_emb[h_tok[node] * DD + lane], 0.f);
    float ai = bs[lane], aj = 0.f, an = 0.f;
#pragma unroll
    for (int k = 0; k < 32; k++) {
        float hk = __shfl_sync(0xffffffffu, hv, k);
        ai += hk * wi[k][lane];
        aj += hk * wj[k][lane];
        an += hk * wn[k][lane];
    }
    g_hi[node * DD + lane] = ai;
    g_hj[node * DD + lane] = aj;
    g_hn[node * DD + lane] = an;
}

// ---------------- launch 2: scan ----------------
__global__ void k_scan() {
    __shared__ int sm[1024];
    int t = threadIdx.x;
    const int CH = (NN + 1023) / 1024;
    int b0 = t * CH;
    int b1 = min(b0 + CH, NN);
    int sum = 0;
    for (int i = b0; i < b1; i++) sum += g_hist[i];
    sm[t] = sum;
    __syncthreads();
    for (int off = 1; off < 1024; off <<= 1) {
        int v = (t >= off) ? sm[t - off] : 0;
        __syncthreads();
        sm[t] += v;
        __syncthreads();
    }
    int pre = sm[t] - sum;
    for (int i = b0; i < b1; i++) {
        g_row[i] = pre;
        g_cursor[i] = pre;
        pre += g_hist[i];
        g_hist[i] = 0;            // re-zero for next call
    }
    if (t == 1023) g_row[NN] = sm[1023];
}

// ---------------- launch 3: fused scatter+gather ----------------
__global__ void k_scatter_gather(const int* __restrict__ src, const int* __restrict__ dst,
                                 const int* __restrict__ e_tok) {
    int i = blockIdx.x * blockDim.x + threadIdx.x;
    if (i >= EE) return;
    int d = dst[i];
    int p = atomicAdd(&g_cursor[d], 1);
    g_srcS[p] = src[i];
    g_dstS[p] = d;
    g_etokS[p] = e_tok[i];
}

// ---------------- edge kernel (tf32 3x-split mma, C-frag f layout) ----------
// flags: bit0 = swap (read g_f/write g_e), bit1 = first (e from token table), bit2 = last (skip f store)
// A is consumed in k-permuted order (slot t <- col 2t, slot t+4 <- col 2t+1);
// B is staged with the SAME row permutation, so the product is exact.
// dyn smem: float4 bfrag[4][4][32] (8KB) | float As[32] | layer0: etab[VOCAB*33]
__global__ void k_edge_mma(const float* __restrict__ Wf, const float* __restrict__ attn,
                           const float* __restrict__ e_emb, int flags) {
    extern __shared__ float4 dsm[];
    float4* bfragP = dsm;                    // ks*128 + nf*32 + lane
    float*  As     = (float*)(dsm + 512);    // 32 floats
    float*  etab   = As + 32;                // VOCAB*33 floats (layer 0 only)
    const int swap = flags & 1, first = flags & 2, lastl = flags & 4;
    int tid = threadIdx.x;
#pragma unroll
    for (int e2 = 0; e2 < 2; e2++) {
        int eid = tid + e2 * 256;
        int ks = eid >> 7, nf = (eid >> 5) & 3, ln = eid & 31;
        // permuted rows: slot (ln&3) <- col ks*8 + 2*(ln&3); slot +4 <- col +1
        int k0 = ks * 8 + 2 * (ln & 3);
        int n  = nf * 8 + (ln >> 2);
        float b0 = Wf[k0 * 32 + n];
        float b1 = Wf[(k0 + 1) * 32 + n];
        unsigned b0b = f2tf32(b0);
        unsigned b0s = f2tf32(b0 - __uint_as_float(b0b));
        unsigned b1b = f2tf32(b1);
        unsigned b1s = f2tf32(b1 - __uint_as_float(b1b));
        bfragP[ks * 128 + nf * 32 + ln] =
            make_float4(__uint_as_float(b0b), __uint_as_float(b0s),
                        __uint_as_float(b1b), __uint_as_float(b1s));
    }
    if (tid < 32) As[tid] = attn[tid];
    if (first) {
        for (int i = tid; i < VOCAB * DD; i += 256)
            etab[(i >> 5) * 33 + (i & 31)] = e_emb[i];
    }
    __syncthreads();

    int warp = tid >> 5;
    int lane = tid & 31;
    int base = (blockIdx.x * 8 + warp) * 16;
    if (base >= EE) return;
    int tile = base >> 4;

    const float4* ein4 = (const float4*)(swap ? g_f : g_e);
    float4*       fout4 = (float4*)(swap ? g_e : g_f);

    int r0 = lane >> 2;
    int t = lane & 3;
    int e0 = base + r0, e1 = e0 + 8;

    int s0 = g_srcS[e0], s1 = g_srcS[e1];
    int d0 = g_dstS[e0], d1 = g_dstS[e1];
    int t0 = 0, t1 = 0;
    if (first) { t0 = g_etokS[e0] * 33; t1 = g_etokS[e1] * 33; }

    float acc[4][4];
#pragma unroll
    for (int nf = 0; nf < 4; nf++)
#pragma unroll
        for (int q = 0; q < 4; q++) acc[nf][q] = 0.f;

#pragma unroll
    for (int ks = 0; ks < 4; ks++) {
        float4 va;   // C-frag order: {(r0,2t),(r0,2t+1),(r1,2t),(r1,2t+1)} within ks group
        if (first) {
            va.x = etab[t0 + ks * 8 + 2 * t];
            va.y = etab[t0 + ks * 8 + 2 * t + 1];
            va.z = etab[t1 + ks * 8 + 2 * t];
            va.w = etab[t1 + ks * 8 + 2 * t + 1];
        } else {
            va = ein4[(size_t)tile * 128 + ks * 32 + lane];
        }
        // A regs: a0=(r0,slot t)=va.x, a1=(r1,slot t)=va.z, a2=(r0,slot t+4)=va.y, a3=(r1,slot t+4)=va.w
        unsigned ab0 = f2tf32(va.x), ab1 = f2tf32(va.z), ab2 = f2tf32(va.y), ab3 = f2tf32(va.w);
        unsigned as0 = f2tf32(va.x - __uint_as_float(ab0));
        unsigned as1 = f2tf32(va.z - __uint_as_float(ab1));
        unsigned as2 = f2tf32(va.y - __uint_as_float(ab2));
        unsigned as3 = f2tf32(va.w - __uint_as_float(ab3));
#pragma unroll
        for (int nf = 0; nf < 4; nf++) {
            float4 bv = bfragP[ks * 128 + nf * 32 + lane];
            unsigned b0b = __float_as_uint(bv.x), b0s = __float_as_uint(bv.y);
            unsigned b1b = __float_as_uint(bv.z), b1s = __float_as_uint(bv.w);
            asm volatile(
                "mma.sync.aligned.m16n8k8.row.col.f32.tf32.tf32.f32 "
                "{%0,%1,%2,%3}, {%4,%5,%6,%7}, {%8,%9}, {%0,%1,%2,%3};"
                : "+f"(acc[nf][0]), "+f"(acc[nf][1]), "+f"(acc[nf][2]), "+f"(acc[nf][3])
                : "r"(ab0), "r"(ab1), "r"(ab2), "r"(ab3), "r"(b0b), "r"(b1b));
            asm volatile(
                "mma.sync.aligned.m16n8k8.row.col.f32.tf32.tf32.f32 "
                "{%0,%1,%2,%3}, {%4,%5,%6,%7}, {%8,%9}, {%0,%1,%2,%3};"
                : "+f"(acc[nf][0]), "+f"(acc[nf][1]), "+f"(acc[nf][2]), "+f"(acc[nf][3])
                : "r"(ab0), "r"(ab1), "r"(ab2), "r"(ab3), "r"(b0s), "r"(b1s));
            asm volatile(
                "mma.sync.aligned.m16n8k8.row.col.f32.tf32.tf32.f32 "
                "{%0,%1,%2,%3}, {%4,%5,%6,%7}, {%8,%9}, {%0,%1,%2,%3};"
                : "+f"(acc[nf][0]), "+f"(acc[nf][1]), "+f"(acc[nf][2]), "+f"(acc[nf][3])
                : "r"(as0), "r"(as1), "r"(as2), "r"(as3), "r"(b0b), "r"(b1b));
        }
    }

    // epilogue: + hi[src] + hj[dst], leakyrelu, logit, direct C-frag store (no shuffles)
    const float2* hi2 = (const float2*)g_hi;
    const float2* hj2 = (const float2*)g_hj;
    float2 hia[4], hja[4], hib[4], hjb[4];
#pragma unroll
    for (int nf = 0; nf < 4; nf++) {
        hia[nf] = hi2[s0 * 16 + nf * 4 + t];
        hja[nf] = hj2[d0 * 16 + nf * 4 + t];
        hib[nf] = hi2[s1 * 16 + nf * 4 + t];
        hjb[nf] = hj2[d1 * 16 + nf * 4 + t];
    }

    float p0 = 0.f, p1 = 0.f;
#pragma unroll
    for (int nf = 0; nf < 4; nf++) {
        int n0 = nf * 8 + t * 2;
        float v0 = acc[nf][0] + hia[nf].x + hja[nf].x;   // (r0, n0)
        float v1 = acc[nf][1] + hia[nf].y + hja[nf].y;   // (r0, n0+1)
        float v2 = acc[nf][2] + hib[nf].x + hjb[nf].x;   // (r1, n0)
        float v3 = acc[nf][3] + hib[nf].y + hjb[nf].y;   // (r1, n0+1)
        v0 = (v0 > 0.f) ? v0 : 0.01f * v0;
        v1 = (v1 > 0.f) ? v1 : 0.01f * v1;
        v2 = (v2 > 0.f) ? v2 : 0.01f * v2;
        v3 = (v3 > 0.f) ? v3 : 0.01f * v3;
        float a0 = As[n0], a1 = As[n0 + 1];
        p0 += v0 * a0 + v1 * a1;
        p1 += v2 * a0 + v3 * a1;
        if (!lastl)
            fout4[(size_t)tile * 128 + nf * 32 + lane] = make_float4(v0, v1, v2, v3);
    }
    p0 += __shfl_xor_sync(0xffffffffu, p0, 1);
    p0 += __shfl_xor_sync(0xffffffffu, p0, 2);
    p1 += __shfl_xor_sync(0xffffffffu, p1, 1);
    p1 += __shfl_xor_sync(0xffffffffu, p1, 2);
    if (t == 0) {
        g_logits[e0] = p0;
        g_logits[e1] = p1;
    }
}

// ---------------- agg (+relu) fused with next layer's projections ----------
__global__ void k_aggproj(const float* __restrict__ Wni, const float* __restrict__ Wnj,
                          const float* __restrict__ Wn, const float* __restrict__ b,
                          int last) {
    __shared__ float wi[32][32], wj[32][32], wn[32][32], bs[32];
    int tid = threadIdx.x;
    if (!last) {
        for (int i = tid; i < 1024; i += 256) {
            wi[i >> 5][i & 31] = Wni[i];
            wj[i >> 5][i & 31] = Wnj[i];
            wn[i >> 5][i & 31] = Wn[i];
        }
        if (tid < 32) bs[tid] = b[tid];
    }
    __syncthreads();
    int node = blockIdx.x * 8 + (tid >> 5);
    int lane = tid & 31;
    if (node >= NN) return;
    int beg = g_row[node], end = g_row[node + 1];
    float m = -1e30f;
    for (int i = beg + lane; i < end; i += 32) m = fmaxf(m, g_logits[i]);
#pragma unroll
    for (int o = 16; o; o >>= 1) m = fmaxf(m, __shfl_xor_sync(0xffffffffu, m, o));
    float s = 0.f, acc = 0.f;
    for (int chunk = beg; chunk < end; chunk += 32) {
        int i = chunk + lane;
        float w = 0.f;
        int sv = 0;
        if (i < end) {
            w = __expf(g_logits[i] - m);
            sv = g_srcS[i];
        }
        s += w;
#pragma unroll
        for (int e = 0; e < 32; e++) {
            float we = __shfl_sync(0xffffffffu, w, e);
            int se = __shfl_sync(0xffffffffu, sv, e);
            acc += we * g_hn[se * DD + lane];
        }
    }
#pragma unroll
    for (int o = 16; o; o >>= 1) s += __shfl_xor_sync(0xffffffffu, s, o);
    float hv = (end > beg) ? fmaxf(acc / s, 0.f) : 0.f;

    if (last) {
        g_h[node * DD + lane] = hv;
        float v = hv;
#pragma unroll
        for (int o = 16; o; o >>= 1) v = fmaxf(v, __shfl_xor_sync(0xffffffffu, v, o));
        if (lane == 0) g_rowmax[node] = v;
    } else {
        float ai = bs[lane], aj = 0.f, an = 0.f;
#pragma unroll
        for (int k = 0; k < 32; k++) {
            float hk = __shfl_sync(0xffffffffu, hv, k);
            ai += hk * wi[k][lane];
            aj += hk * wj[k][lane];
            an += hk * wn[k][lane];
        }
        g_hi[node * DD + lane] = ai;
        g_hj[node * DD + lane] = aj;
        g_hn[node * DD + lane] = an;
    }
}

// ---------------- SortPooling + MLP head ----------------
__global__ void k_head(const float* __restrict__ Wlin, const float* __restrict__ blin,
                       const float* __restrict__ W1, const float* __restrict__ b1,
                       const float* __restrict__ W2, const float* __restrict__ b2,
                       const float* __restrict__ Wc, const float* __restrict__ bc,
                       float* __restrict__ out) {
    __shared__ float sv[256];
    __shared__ int si[256];
    __shared__ int picked[TOPK];
    __shared__ float xs[TOPK * DD];
    __shared__ float y1[32], y2[32], y3[32];
    int tid = threadIdx.x;

    for (int t = 0; t < TOPK; t++) {
        float best = -1e30f;
        int bidx = 0x7fffffff;
        for (int i = tid; i < NN; i += 256) {
            bool skip = false;
            for (int p = 0; p < t; p++)
                if (picked[p] == i) skip = true;
            if (skip) continue;
            float v = g_rowmax[i];
            if (v > best || (v == best && i < bidx)) { best = v; bidx = i; }
        }
        sv[tid] = best;
        si[tid] = bidx;
        __syncthreads();
        for (int off = 128; off; off >>= 1) {
            if (tid < off) {
                float v2 = sv[tid + off];
                int i2 = si[tid + off];
                if (v2 > sv[tid] || (v2 == sv[tid] && i2 < si[tid])) {
                    sv[tid] = v2;
                    si[tid] = i2;
                }
            }
            __syncthreads();
        }
        if (tid == 0) picked[t] = si[0];
        __syncthreads();
    }

    if (tid < TOPK) {
        float r[32];
        int n = picked[tid];
        for (int d = 0; d < 32; d++) r[d] = g_h[n * DD + d];
        for (int a = 1; a < 32; a++) {
            float key = r[a];
            int b = a - 1;
            while (b >= 0 && r[b] > key) { r[b + 1] = r[b]; b--; }
            r[b + 1] = key;
        }
        for (int d = 0; d < 32; d++) xs[tid * 32 + d] = r[d];
    }
    __syncthreads();

    if (tid < 32) {
        float a = blin[tid];
        for (int i = 0; i < 256; i++) a += xs[i] * Wlin[i * 32 + tid];
        y1[tid] = fmaxf(a, 0.f);
    }
    __syncthreads();
    if (tid < 32) {
        float a = b1[tid];
        for (int k = 0; k < 32; k++) a += y1[k] * W1[k * 32 + tid];
        y2[tid] = fmaxf(a, 0.f);
    }
    __syncthreads();
    if (tid < 32) {
        float a = b2[tid];
        for (int k = 0; k < 32; k++) a += y2[k] * W2[k * 32 + tid];
        y3[tid] = fmaxf(a, 0.f);
    }
    __syncthreads();
    if (tid < 2) {
        float a = bc[tid];
        for (int k = 0; k < 32; k++) a += y3[k] * Wc[k * 2 + tid];
        out[tid] = a;
    }
}

// ---------------- launch ----------------
extern "C" void kernel_launch(void* const* d_in, const int* in_sizes, int n_in,
                              void* d_out, int out_size) {
    (void)in_sizes; (void)n_in; (void)out_size;
    const int*   h_tok     = (const int*)d_in[0];
    const int*   e_tok     = (const int*)d_in[1];
    const int*   src       = (const int*)d_in[2];
    const int*   dst       = (const int*)d_in[3];
    const float* tok_emb   = (const float*)d_in[4];
    const float* e_tok_emb = (const float*)d_in[5];
    const float* W_ni      = (const float*)d_in[6];
    const float* W_nj      = (const float*)d_in[7];
    const float* W_fij     = (const float*)d_in[8];
    const float* b_edge    = (const float*)d_in[9];
    const float* attn      = (const float*)d_in[10];
    const float* W_node    = (const float*)d_in[11];
    const float* W_lin     = (const float*)d_in[12];
    const float* b_lin     = (const float*)d_in[13];
    const float* W1        = (const float*)d_in[14];
    const float* b1        = (const float*)d_in[15];
    const float* W2        = (const float*)d_in[16];
    const float* b2        = (const float*)d_in[17];
    const float* Wc        = (const float*)d_in[18];
    const float* bc        = (const float*)d_in[19];
    float* out = (float*)d_out;

    const int MB = (EE + 127) / 128;                      // 12500
    const size_t SM_BASE  = 512 * 16 + 32 * 4;            // 8320
    const size_t SM_FIRST = SM_BASE + VOCAB * 33 * 4;     // 21520

    k_hist_init<<<EB + WB, 256>>>(dst, h_tok, tok_emb, W_ni, W_nj, W_node, b_edge);
    k_scan<<<1, 1024>>>();
    k_scatter_gather<<<EB, 256>>>(src, dst, e_tok);

    for (int l = 0; l < NLAYERS; l++) {
        int flags = (l & 1) | ((l == 0) ? 2 : 0) | ((l == NLAYERS - 1) ? 4 : 0);
        k_edge_mma<<<MB, 256, (l == 0) ? SM_FIRST : SM_BASE>>>(
            W_fij + l * 1024, attn + l * 32, e_tok_emb, flags);
        if (l < NLAYERS - 1) {
            k_aggproj<<<WB, 256>>>(W_ni + (l + 1) * 1024, W_nj + (l + 1) * 1024,
                                   W_node + (l + 1) * 1024, b_edge + (l + 1) * 32, 0);
        } else {
            k_aggproj<<<WB, 256>>>(W_ni, W_nj, W_node, b_edge, 1);
        }
    }

    k_head<<<1, 256>>>(W_lin, b_lin, W1, b1, W2, b2, Wc, bc, out);
}